// round 2
// baseline (speedup 1.0000x reference)
#include <cuda_runtime.h>

#define NU 100000
#define NV 50000
#define NN 150000
#define DD 64
#define NE 2000000
#define ALPHA (1.0f/3.0f)

#define SCAN_B 256
#define NBLK_SCAN ((NN + SCAN_B - 1) / SCAN_B)   // 586

// ---- device scratch (allocation-free rule: static __device__ globals) ----
__device__ float g_E[NN * DD];     // ego_pos (concat user,item)
__device__ float g_A[NN * DD];     // h1_p
__device__ float g_B[NN * DD];     // h1_n
__device__ int   g_cnt_p[NN];
__device__ int   g_cnt_n[NN];
__device__ int   g_off_p[NN];
__device__ int   g_off_n[NN];
__device__ int   g_cur_p[NN];
__device__ int   g_cur_n[NN];
__device__ int   g_src_p[NE];
__device__ int   g_src_n[NE];
__device__ int   g_part_p[1024];
__device__ int   g_part_n[1024];

// ---- K0: ego copy (float4) + zero counters ----
__global__ void k_init(const float4* __restrict__ ue, const float4* __restrict__ ie) {
    int i = blockIdx.x * blockDim.x + threadIdx.x;
    const int total4 = NN * DD / 4;
    if (i < total4) {
        int g = i * 4;
        int n = g >> 6;
        int c4 = (g & 63) >> 2;
        float4 v = (n < NU) ? ue[n * (DD / 4) + c4]
                            : ie[(n - NU) * (DD / 4) + c4];
        reinterpret_cast<float4*>(g_E)[i] = v;
    }
    if (i < NN) { g_cnt_p[i] = 0; g_cnt_n[i] = 0; }
}

// ---- K1: degree histograms (2 edges/thread) ----
__global__ void k_hist(const int* __restrict__ pd, const int* __restrict__ nd) {
    int e = (blockIdx.x * blockDim.x + threadIdx.x) * 2;
    if (e < NE) {
        int2 d1 = *reinterpret_cast<const int2*>(pd + e);
        atomicAdd(&g_cnt_p[d1.x], 1);
        atomicAdd(&g_cnt_p[d1.y], 1);
        int2 d2 = *reinterpret_cast<const int2*>(nd + e);
        atomicAdd(&g_cnt_n[d2.x], 1);
        atomicAdd(&g_cnt_n[d2.y], 1);
    }
}

// ---- K2a: per-block exclusive scan of counts ----
__global__ void k_scan1() {
    __shared__ int s[SCAN_B];
    int list = blockIdx.y;
    const int* cnt = list ? g_cnt_n : g_cnt_p;
    int* off       = list ? g_off_n : g_off_p;
    int* part      = list ? g_part_n : g_part_p;

    int gid = blockIdx.x * SCAN_B + threadIdx.x;
    int v = (gid < NN) ? cnt[gid] : 0;
    int x = v;
    s[threadIdx.x] = x;
    __syncthreads();
    for (int o = 1; o < SCAN_B; o <<= 1) {
        int t = (threadIdx.x >= o) ? s[threadIdx.x - o] : 0;
        __syncthreads();
        x += t;
        s[threadIdx.x] = x;
        __syncthreads();
    }
    if (gid < NN) off[gid] = x - v;
    if (threadIdx.x == SCAN_B - 1) part[blockIdx.x] = x;
}

// ---- K2b: parallel exclusive scan of block partials ----
__global__ void k_scan2() {
    __shared__ int s[1024];
    int* part = blockIdx.x ? g_part_n : g_part_p;
    int t = threadIdx.x;
    int v = (t < NBLK_SCAN) ? part[t] : 0;
    int x = v;
    s[t] = x;
    __syncthreads();
    for (int o = 1; o < 1024; o <<= 1) {
        int tt = (t >= o) ? s[t - o] : 0;
        __syncthreads();
        x += tt;
        s[t] = x;
        __syncthreads();
    }
    if (t < NBLK_SCAN) part[t] = x - v;   // exclusive
}

// ---- K2c: finalize offsets; init fill cursors ----
__global__ void k_scan3() {
    int gid = blockIdx.x * SCAN_B + threadIdx.x;
    if (gid >= NN) return;
    if (blockIdx.y == 0) {
        int o = g_off_p[gid] + g_part_p[gid >> 8];
        g_off_p[gid] = o; g_cur_p[gid] = o;
    } else {
        int o = g_off_n[gid] + g_part_n[gid >> 8];
        g_off_n[gid] = o; g_cur_n[gid] = o;
    }
}

// ---- K3: counting-sort fill (2 edges/thread) ----
__global__ void k_fill(const int* __restrict__ ps, const int* __restrict__ pd,
                       const int* __restrict__ ns, const int* __restrict__ nd) {
    int e = (blockIdx.x * blockDim.x + threadIdx.x) * 2;
    if (e < NE) {
        int2 s1 = *reinterpret_cast<const int2*>(ps + e);
        int2 d1 = *reinterpret_cast<const int2*>(pd + e);
        g_src_p[atomicAdd(&g_cur_p[d1.x], 1)] = s1.x;
        g_src_p[atomicAdd(&g_cur_p[d1.y], 1)] = s1.y;
        int2 s2 = *reinterpret_cast<const int2*>(ns + e);
        int2 d2 = *reinterpret_cast<const int2*>(nd + e);
        g_src_n[atomicAdd(&g_cur_n[d2.x], 1)] = s2.x;
        g_src_n[atomicAdd(&g_cur_n[d2.y], 1)] = s2.y;
    }
}

// ---- gather: half-warp float4, interleaved edge assignment ----
// lane = h*16+hl; half h processes edges (2k+h); acc is per-half partial.
__device__ __forceinline__ void gather_accum4(const float4* __restrict__ X,
                                              const int* __restrict__ srclist,
                                              int start, int cnt,
                                              int lane, int h, int hl,
                                              float4& acc) {
    for (int base = 0; base < cnt; base += 32) {
        int rem = cnt - base;
        int m = rem < 32 ? rem : 32;
        int idx = 0;
        if (lane < m) idx = __ldg(&srclist[start + base + lane]);
        int iters = (m + 1) >> 1;
        #pragma unroll 4
        for (int k = 0; k < iters; k++) {
            int j = 2 * k + h;
            int sidx = __shfl_sync(0xffffffffu, idx, j & 31);
            if (j < m) {
                float4 v = X[sidx * 16 + hl];
                acc.x += v.x; acc.y += v.y; acc.z += v.z; acc.w += v.w;
            }
        }
    }
}

__device__ __forceinline__ void combine_halves(float4& a) {
    a.x += __shfl_xor_sync(0xffffffffu, a.x, 16);
    a.y += __shfl_xor_sync(0xffffffffu, a.y, 16);
    a.z += __shfl_xor_sync(0xffffffffu, a.z, 16);
    a.w += __shfl_xor_sync(0xffffffffu, a.w, 16);
}

// ---- K4: layer 1 fused ----
__global__ void __launch_bounds__(256) k_conv1(const float* __restrict__ un,
                                               const float* __restrict__ inn,
                                               float* __restrict__ out) {
    int warp = (blockIdx.x * blockDim.x + threadIdx.x) >> 5;
    int lane = threadIdx.x & 31;
    if (warp >= NN) return;
    int node = warp;
    int h = lane >> 4, hl = lane & 15;

    const float4* E4 = reinterpret_cast<const float4*>(g_E);

    float4 ap = make_float4(0.f, 0.f, 0.f, 0.f);
    float4 an = make_float4(0.f, 0.f, 0.f, 0.f);
    gather_accum4(E4, g_src_p, g_off_p[node], g_cnt_p[node], lane, h, hl, ap);
    gather_accum4(E4, g_src_n, g_off_n[node], g_cnt_n[node], lane, h, hl, an);
    combine_halves(ap);
    combine_halves(an);

    if (h == 0) {
        float4 ego = E4[node * 16 + hl];
        float4 egon = (node < NU)
            ? reinterpret_cast<const float4*>(un)[node * 16 + hl]
            : reinterpret_cast<const float4*>(inn)[(node - NU) * 16 + hl];

        // h1 = ego + agg
        float4 h1p, h1n;
        h1p.x = ego.x + ap.x; h1p.y = ego.y + ap.y; h1p.z = ego.z + ap.z; h1p.w = ego.w + ap.w;
        h1n.x = ego.x + an.x; h1n.y = ego.y + an.y; h1n.z = ego.z + an.z; h1n.w = ego.w + an.w;
        reinterpret_cast<float4*>(g_A)[node * 16 + hl] = h1p;
        reinterpret_cast<float4*>(g_B)[node * 16 + hl] = h1n;

        float4 op, on;
        op.x = ALPHA * (ego.x + h1p.x);  op.y = ALPHA * (ego.y + h1p.y);
        op.z = ALPHA * (ego.z + h1p.z);  op.w = ALPHA * (ego.w + h1p.w);
        on.x = ALPHA * (egon.x + h1n.x); on.y = ALPHA * (egon.y + h1n.y);
        on.z = ALPHA * (egon.z + h1n.z); on.w = ALPHA * (egon.w + h1n.w);
        reinterpret_cast<float4*>(out)[node * 16 + hl] = op;
        reinterpret_cast<float4*>(out + (size_t)NN * DD)[node * 16 + hl] = on;
    }
}

// ---- K5: layer 2 fused ----
__global__ void __launch_bounds__(256) k_conv2(float* __restrict__ out) {
    int warp = (blockIdx.x * blockDim.x + threadIdx.x) >> 5;
    int lane = threadIdx.x & 31;
    if (warp >= NN) return;
    int node = warp;
    int h = lane >> 4, hl = lane & 15;

    const float4* A4 = reinterpret_cast<const float4*>(g_A);
    const float4* B4 = reinterpret_cast<const float4*>(g_B);

    float4 ap = make_float4(0.f, 0.f, 0.f, 0.f);
    float4 an = make_float4(0.f, 0.f, 0.f, 0.f);
    gather_accum4(A4, g_src_p, g_off_p[node], g_cnt_p[node], lane, h, hl, ap);
    gather_accum4(B4, g_src_n, g_off_n[node], g_cnt_n[node], lane, h, hl, an);
    combine_halves(ap);
    combine_halves(an);

    if (h == 0) {
        float4 s1 = A4[node * 16 + hl];
        float4 s2 = B4[node * 16 + hl];
        float4* outp = reinterpret_cast<float4*>(out);
        float4* outn = reinterpret_cast<float4*>(out + (size_t)NN * DD);
        float4 pp = outp[node * 16 + hl];
        float4 pn = outn[node * 16 + hl];
        pp.x += ALPHA * (s1.x + ap.x);  pp.y += ALPHA * (s1.y + ap.y);
        pp.z += ALPHA * (s1.z + ap.z);  pp.w += ALPHA * (s1.w + ap.w);
        pn.x += ALPHA * (s2.x + an.x);  pn.y += ALPHA * (s2.y + an.y);
        pn.z += ALPHA * (s2.z + an.z);  pn.w += ALPHA * (s2.w + an.w);
        outp[node * 16 + hl] = pp;
        outn[node * 16 + hl] = pn;
    }
}

extern "C" void kernel_launch(void* const* d_in, const int* in_sizes, int n_in,
                              void* d_out, int out_size) {
    const float* ue  = (const float*)d_in[0];
    const float* ie  = (const float*)d_in[1];
    const float* un  = (const float*)d_in[2];
    const float* inn = (const float*)d_in[3];
    const int* pe    = (const int*)d_in[4];
    const int* ne    = (const int*)d_in[5];
    float* out = (float*)d_out;

    const int* ps = pe;        const int* pd = pe + NE;
    const int* ns = ne;        const int* nd = ne + NE;

    {
        int total4 = NN * DD / 4;
        int blk = (total4 + 255) / 256;
        k_init<<<blk, 256>>>((const float4*)ue, (const float4*)ie);
    }
    k_hist<<<(NE / 2 + 255) / 256, 256>>>(pd, nd);
    {
        dim3 g1(NBLK_SCAN, 2);
        k_scan1<<<g1, SCAN_B>>>();
        k_scan2<<<2, 1024>>>();
        k_scan3<<<g1, SCAN_B>>>();
    }
    k_fill<<<(NE / 2 + 255) / 256, 256>>>(ps, pd, ns, nd);

    int conv_blocks = NN / 8;   // warp per node, 8 warps/block
    k_conv1<<<conv_blocks, 256>>>(un, inn, out);
    k_conv2<<<conv_blocks, 256>>>(out);
}

// round 3
// speedup vs baseline: 1.0440x; 1.0440x over previous
#include <cuda_runtime.h>

#define NU 100000
#define NV 50000
#define NN 150000
#define DD 64
#define NE 2000000
#define ALPHA (1.0f/3.0f)

#define SCAN_B 256
#define NBLK_SCAN ((NN + SCAN_B - 1) / SCAN_B)   // 586

// ---- device scratch (allocation-free rule: static __device__ globals) ----
__device__ float g_E[NN * DD];     // ego_pos (concat user,item)
__device__ float g_A[NN * DD];     // h1_p
__device__ float g_B[NN * DD];     // h1_n
__device__ int   g_cnt_p[NN];
__device__ int   g_cnt_n[NN];
__device__ int   g_off_p[NN];
__device__ int   g_off_n[NN];
__device__ int   g_cur_p[NN];
__device__ int   g_cur_n[NN];
__device__ int   g_src_p[NE];
__device__ int   g_src_n[NE];
__device__ int   g_part_p[1024];
__device__ int   g_part_n[1024];

// ---- K0: ego copy (float4) + zero counters ----
__global__ void k_init(const float4* __restrict__ ue, const float4* __restrict__ ie) {
    int i = blockIdx.x * blockDim.x + threadIdx.x;
    const int total4 = NN * DD / 4;
    if (i < total4) {
        int g = i * 4;
        int n = g >> 6;
        int c4 = (g & 63) >> 2;
        float4 v = (n < NU) ? ue[n * (DD / 4) + c4]
                            : ie[(n - NU) * (DD / 4) + c4];
        reinterpret_cast<float4*>(g_E)[i] = v;
    }
    if (i < NN) { g_cnt_p[i] = 0; g_cnt_n[i] = 0; }
}

// ---- K1: degree histograms (2 edges/thread) ----
__global__ void k_hist(const int* __restrict__ pd, const int* __restrict__ nd) {
    int e = (blockIdx.x * blockDim.x + threadIdx.x) * 2;
    if (e < NE) {
        int2 d1 = __ldcs(reinterpret_cast<const int2*>(pd + e));
        atomicAdd(&g_cnt_p[d1.x], 1);
        atomicAdd(&g_cnt_p[d1.y], 1);
        int2 d2 = __ldcs(reinterpret_cast<const int2*>(nd + e));
        atomicAdd(&g_cnt_n[d2.x], 1);
        atomicAdd(&g_cnt_n[d2.y], 1);
    }
}

// ---- K2a: per-block exclusive scan of counts ----
__global__ void k_scan1() {
    __shared__ int s[SCAN_B];
    int list = blockIdx.y;
    const int* cnt = list ? g_cnt_n : g_cnt_p;
    int* off       = list ? g_off_n : g_off_p;
    int* part      = list ? g_part_n : g_part_p;

    int gid = blockIdx.x * SCAN_B + threadIdx.x;
    int v = (gid < NN) ? cnt[gid] : 0;
    int x = v;
    s[threadIdx.x] = x;
    __syncthreads();
    for (int o = 1; o < SCAN_B; o <<= 1) {
        int t = (threadIdx.x >= o) ? s[threadIdx.x - o] : 0;
        __syncthreads();
        x += t;
        s[threadIdx.x] = x;
        __syncthreads();
    }
    if (gid < NN) off[gid] = x - v;
    if (threadIdx.x == SCAN_B - 1) part[blockIdx.x] = x;
}

// ---- K2b: parallel exclusive scan of block partials ----
__global__ void k_scan2() {
    __shared__ int s[1024];
    int* part = blockIdx.x ? g_part_n : g_part_p;
    int t = threadIdx.x;
    int v = (t < NBLK_SCAN) ? part[t] : 0;
    int x = v;
    s[t] = x;
    __syncthreads();
    for (int o = 1; o < 1024; o <<= 1) {
        int tt = (t >= o) ? s[t - o] : 0;
        __syncthreads();
        x += tt;
        s[t] = x;
        __syncthreads();
    }
    if (t < NBLK_SCAN) part[t] = x - v;   // exclusive
}

// ---- K2c: finalize offsets; init fill cursors ----
__global__ void k_scan3() {
    int gid = blockIdx.x * SCAN_B + threadIdx.x;
    if (gid >= NN) return;
    if (blockIdx.y == 0) {
        int o = g_off_p[gid] + g_part_p[gid >> 8];
        g_off_p[gid] = o; g_cur_p[gid] = o;
    } else {
        int o = g_off_n[gid] + g_part_n[gid >> 8];
        g_off_n[gid] = o; g_cur_n[gid] = o;
    }
}

// ---- K3: counting-sort fill (2 edges/thread) ----
__global__ void k_fill(const int* __restrict__ ps, const int* __restrict__ pd,
                       const int* __restrict__ ns, const int* __restrict__ nd) {
    int e = (blockIdx.x * blockDim.x + threadIdx.x) * 2;
    if (e < NE) {
        int2 s1 = __ldcs(reinterpret_cast<const int2*>(ps + e));
        int2 d1 = __ldcs(reinterpret_cast<const int2*>(pd + e));
        g_src_p[atomicAdd(&g_cur_p[d1.x], 1)] = s1.x;
        g_src_p[atomicAdd(&g_cur_p[d1.y], 1)] = s1.y;
        int2 s2 = __ldcs(reinterpret_cast<const int2*>(ns + e));
        int2 d2 = __ldcs(reinterpret_cast<const int2*>(nd + e));
        g_src_n[atomicAdd(&g_cur_n[d2.x], 1)] = s2.x;
        g_src_n[atomicAdd(&g_cur_n[d2.y], 1)] = s2.y;
    }
}

// ---- gather: warp-wide float2 broadcast, dual accumulators for MLP ----
__device__ __forceinline__ void gather_accum(const float2* __restrict__ X,
                                             const int* __restrict__ srclist,
                                             int start, int cnt, int lane,
                                             float2& acc0, float2& acc1) {
    for (int base = 0; base < cnt; base += 32) {
        int rem = cnt - base;
        int m = rem < 32 ? rem : 32;
        int idx = (lane < m) ? __ldcs(&srclist[start + base + lane]) : 0;
        int kfull = m & ~1;
        #pragma unroll 4
        for (int k = 0; k < kfull; k += 2) {
            int j0 = __shfl_sync(0xffffffffu, idx, k);
            int j1 = __shfl_sync(0xffffffffu, idx, k + 1);
            float2 v0 = X[j0 * 32 + lane];
            float2 v1 = X[j1 * 32 + lane];
            acc0.x += v0.x; acc0.y += v0.y;
            acc1.x += v1.x; acc1.y += v1.y;
        }
        if (m & 1) {
            int j = __shfl_sync(0xffffffffu, idx, m - 1);
            float2 v = X[j * 32 + lane];
            acc0.x += v.x; acc0.y += v.y;
        }
    }
}

// ---- K4: layer 1 fused (pos+neg conv, acc init, self-term) ----
__global__ void __launch_bounds__(256) k_conv1(const float* __restrict__ un,
                                               const float* __restrict__ inn,
                                               float* __restrict__ out) {
    int warp = (blockIdx.x * blockDim.x + threadIdx.x) >> 5;
    int lane = threadIdx.x & 31;
    if (warp >= NN) return;
    int node = warp;

    const float2* E2 = reinterpret_cast<const float2*>(g_E);
    float2 ego = E2[node * 32 + lane];

    float2 ap0 = make_float2(0.f, 0.f), ap1 = make_float2(0.f, 0.f);
    float2 an0 = make_float2(0.f, 0.f), an1 = make_float2(0.f, 0.f);
    gather_accum(E2, g_src_p, g_off_p[node], g_cnt_p[node], lane, ap0, ap1);
    gather_accum(E2, g_src_n, g_off_n[node], g_cnt_n[node], lane, an0, an1);

    // h1 = ego + agg
    float2 h1p, h1n;
    h1p.x = ego.x + ap0.x + ap1.x;  h1p.y = ego.y + ap0.y + ap1.y;
    h1n.x = ego.x + an0.x + an1.x;  h1n.y = ego.y + an0.y + an1.y;

    // stream h1 stores (read next kernel, not this one) — keep g_E resident
    __stcs(reinterpret_cast<float2*>(g_A) + node * 32 + lane, h1p);
    __stcs(reinterpret_cast<float2*>(g_B) + node * 32 + lane, h1n);

    float2 egon = (node < NU)
        ? reinterpret_cast<const float2*>(un)[node * 32 + lane]
        : reinterpret_cast<const float2*>(inn)[(node - NU) * 32 + lane];

    float2 op, on;
    op.x = ALPHA * (ego.x + h1p.x);  op.y = ALPHA * (ego.y + h1p.y);
    on.x = ALPHA * (egon.x + h1n.x); on.y = ALPHA * (egon.y + h1n.y);
    __stwt(reinterpret_cast<float2*>(out) + node * 32 + lane, op);
    __stwt(reinterpret_cast<float2*>(out + (size_t)NN * DD) + node * 32 + lane, on);
}

// ---- K5: layer 2 fused (gather from h1, final acc) ----
__global__ void __launch_bounds__(256) k_conv2(float* __restrict__ out) {
    int warp = (blockIdx.x * blockDim.x + threadIdx.x) >> 5;
    int lane = threadIdx.x & 31;
    if (warp >= NN) return;
    int node = warp;

    const float2* A2 = reinterpret_cast<const float2*>(g_A);
    const float2* B2 = reinterpret_cast<const float2*>(g_B);

    float2 ap0 = A2[node * 32 + lane], ap1 = make_float2(0.f, 0.f);
    float2 an0 = B2[node * 32 + lane], an1 = make_float2(0.f, 0.f);
    gather_accum(A2, g_src_p, g_off_p[node], g_cnt_p[node], lane, ap0, ap1);
    gather_accum(B2, g_src_n, g_off_n[node], g_cnt_n[node], lane, an0, an1);

    float2* outp = reinterpret_cast<float2*>(out);
    float2* outn = reinterpret_cast<float2*>(out + (size_t)NN * DD);
    float2 pp = __ldcs(outp + node * 32 + lane);   // read-once stream
    float2 pn = __ldcs(outn + node * 32 + lane);
    pp.x += ALPHA * (ap0.x + ap1.x);  pp.y += ALPHA * (ap0.y + ap1.y);
    pn.x += ALPHA * (an0.x + an1.x);  pn.y += ALPHA * (an0.y + an1.y);
    __stwt(outp + node * 32 + lane, pp);
    __stwt(outn + node * 32 + lane, pn);
}

extern "C" void kernel_launch(void* const* d_in, const int* in_sizes, int n_in,
                              void* d_out, int out_size) {
    const float* ue  = (const float*)d_in[0];
    const float* ie  = (const float*)d_in[1];
    const float* un  = (const float*)d_in[2];
    const float* inn = (const float*)d_in[3];
    const int* pe    = (const int*)d_in[4];
    const int* ne    = (const int*)d_in[5];
    float* out = (float*)d_out;

    const int* ps = pe;        const int* pd = pe + NE;
    const int* ns = ne;        const int* nd = ne + NE;

    {
        int total4 = NN * DD / 4;
        int blk = (total4 + 255) / 256;
        k_init<<<blk, 256>>>((const float4*)ue, (const float4*)ie);
    }
    k_hist<<<(NE / 2 + 255) / 256, 256>>>(pd, nd);
    {
        dim3 g1(NBLK_SCAN, 2);
        k_scan1<<<g1, SCAN_B>>>();
        k_scan2<<<2, 1024>>>();
        k_scan3<<<g1, SCAN_B>>>();
    }
    k_fill<<<(NE / 2 + 255) / 256, 256>>>(ps, pd, ns, nd);

    int conv_blocks = NN / 8;   // warp per node, 8 warps/block
    k_conv1<<<conv_blocks, 256>>>(un, inn, out);
    k_conv2<<<conv_blocks, 256>>>(out);
}